// round 3
// baseline (speedup 1.0000x reference)
#include <cuda_runtime.h>

#define BQ    4          // batches
#define NQ    8192       // points per cloud
#define RC    4          // ref chunks
#define QT    8          // query tiles per batch
#define TPB   256        // threads per block
#define QPT   4          // queries per thread  (QT*TPB*QPT == NQ)
#define CHUNK (NQ / RC)  // 2048 refs per chunk
#define CHUNK2 (CHUNK / 2)

// Phase-1 scratch: s = q^2/2 + min_chunk(r^2/2 - q.r), per [batch][chunk][query]
__device__ float g_smin[BQ * RC * NQ];

__device__ __forceinline__ unsigned long long pack2(float a, float b) {
    unsigned long long r;
    asm("mov.b64 %0, {%1, %2};" : "=l"(r) : "f"(a), "f"(b));
    return r;
}
__device__ __forceinline__ unsigned long long ffma2(unsigned long long a,
                                                    unsigned long long b,
                                                    unsigned long long c) {
    unsigned long long d;
    asm("fma.rn.f32x2 %0, %1, %2, %3;" : "=l"(d) : "l"(a), "l"(b), "l"(c));
    return d;
}
__device__ __forceinline__ float lo32(unsigned long long v) {
    return __uint_as_float((unsigned)v);
}
__device__ __forceinline__ float hi32(unsigned long long v) {
    return __uint_as_float((unsigned)(v >> 32));
}

// Phase 1: each block = (batch b, query tile qt, ref chunk rc).
// Computes, for its 1024 queries, min over its 2048 refs of (r^2/2 - q.r),
// stores s = q^2/2 + min  into g_smin.
__global__ __launch_bounds__(TPB) void chamfer_phase1(
    const float* __restrict__ pc2,       // queries  [B,3,N]
    const float* __restrict__ pc1w) {    // refs     [B,3,N]
    int blk = blockIdx.x;
    int rc = blk % RC;
    int qt = (blk / RC) % QT;
    int b  = blk / (RC * QT);

    const float* __restrict__ qry = pc2  + b * 3 * NQ;
    const float* __restrict__ ref = pc1w + b * 3 * NQ;

    __shared__ float sx[CHUNK];
    __shared__ float sy[CHUNK];
    __shared__ float sz[CHUNK];
    __shared__ float sh[CHUNK];   // r^2 / 2

    int tid = threadIdx.x;
    int rbase = rc * CHUNK;

    // Cooperative load of the ref chunk (coalesced; channel-major layout).
    for (int i = tid; i < CHUNK; i += TPB) {
        float x = ref[rbase + i];
        float y = ref[NQ + rbase + i];
        float z = ref[2 * NQ + rbase + i];
        sx[i] = x; sy[i] = y; sz[i] = z;
        sh[i] = 0.5f * (x * x + y * y + z * z);
    }
    __syncthreads();

    // Per-thread register tile of QPT queries (broadcast as packed f32x2).
    unsigned long long nqx[QPT], nqy[QPT], nqz[QPT];
    float q2h[QPT];
    int qidx[QPT];
#pragma unroll
    for (int q = 0; q < QPT; q++) {
        int qi = qt * (TPB * QPT) + q * TPB + tid;
        qidx[q] = qi;
        float x = qry[qi];
        float y = qry[NQ + qi];
        float z = qry[2 * NQ + qi];
        nqx[q] = pack2(-x, -x);
        nqy[q] = pack2(-y, -y);
        nqz[q] = pack2(-z, -z);
        q2h[q] = 0.5f * (x * x + y * y + z * z);
    }

    float m0[QPT], m1[QPT];
#pragma unroll
    for (int q = 0; q < QPT; q++) { m0[q] = 3.0e38f; m1[q] = 3.0e38f; }

    const unsigned long long* __restrict__ px = (const unsigned long long*)sx;
    const unsigned long long* __restrict__ py = (const unsigned long long*)sy;
    const unsigned long long* __restrict__ pz = (const unsigned long long*)sz;
    const unsigned long long* __restrict__ ph = (const unsigned long long*)sh;

    // Main loop: 2 refs (packed) x QPT queries per iteration.
    // Per packed iter: 4x LDS.64 + QPT*3 FFMA2 + QPT*2 FMNMX.
#pragma unroll 4
    for (int j = 0; j < CHUNK2; j++) {
        unsigned long long X = px[j];
        unsigned long long Y = py[j];
        unsigned long long Z = pz[j];
        unsigned long long H = ph[j];
#pragma unroll
        for (int q = 0; q < QPT; q++) {
            unsigned long long t = ffma2(nqx[q], X, H);
            t = ffma2(nqy[q], Y, t);
            t = ffma2(nqz[q], Z, t);   // t = r^2/2 - q.r  (two refs)
            m0[q] = fminf(m0[q], lo32(t));
            m1[q] = fminf(m1[q], hi32(t));
        }
    }

#pragma unroll
    for (int q = 0; q < QPT; q++) {
        g_smin[(b * RC + rc) * NQ + qidx[q]] = q2h[q] + fminf(m0[q], m1[q]);
    }
}

// Phase 2: single block. Min over ref chunks, clamp, deterministic tree sum,
// final scale: loss = 2 * mean_b(sum_n nn) = (2/B) * total.
__global__ __launch_bounds__(1024) void chamfer_phase2(float* __restrict__ out) {
    __shared__ float red[1024];
    int tid = threadIdx.x;
    float acc = 0.0f;
    for (int i = tid; i < BQ * NQ; i += 1024) {
        int b  = i / NQ;
        int qi = i - b * NQ;
        const float* p = &g_smin[b * RC * NQ + qi];
        float s = p[0];
#pragma unroll
        for (int c = 1; c < RC; c++) s = fminf(s, p[c * NQ]);
        acc += fmaxf(2.0f * s, 0.0f);   // nn squared dist, clamped at 0
    }
    red[tid] = acc;
    __syncthreads();
#pragma unroll
    for (int s = 512; s > 0; s >>= 1) {
        if (tid < s) red[tid] += red[tid + s];
        __syncthreads();
    }
    if (tid == 0) out[0] = red[0] * (2.0f / BQ);
}

extern "C" void kernel_launch(void* const* d_in, const int* in_sizes, int n_in,
                              void* d_out, int out_size) {
    const float* pc2  = (const float*)d_in[0];   // queries source
    const float* pc1w = (const float*)d_in[1];   // refs source
    float* out = (float*)d_out;

    chamfer_phase1<<<BQ * QT * RC, TPB>>>(pc2, pc1w);
    chamfer_phase2<<<1, 1024>>>(out);
}

// round 5
// speedup vs baseline: 1.9902x; 1.9902x over previous
#include <cuda_runtime.h>

#define BQ    4           // batches
#define NQ    8192        // points per cloud
#define TPB   512         // threads per block (phase 1)
#define QPT   4           // queries per thread
#define QT    4           // query tiles per batch  (QT*TPB*QPT == NQ)
#define RC    8           // ref chunks
#define CHUNK (NQ / RC)   // 1024 refs per chunk
#define CHUNK4 (CHUNK / 4)

// Phase-1 scratch: s = q^2/2 + min_chunk(r^2/2 - q.r), per [batch][chunk][query]
__device__ float g_smin[BQ * RC * NQ];
// Phase-2a partials (one per phase-2a block)
__device__ float g_part[128];

__device__ __forceinline__ unsigned long long pack2(float a, float b) {
    unsigned long long r;
    asm("mov.b64 %0, {%1, %2};" : "=l"(r) : "f"(a), "f"(b));
    return r;
}
__device__ __forceinline__ unsigned long long ffma2(unsigned long long a,
                                                    unsigned long long b,
                                                    unsigned long long c) {
    unsigned long long d;
    asm("fma.rn.f32x2 %0, %1, %2, %3;" : "=l"(d) : "l"(a), "l"(b), "l"(c));
    return d;
}
__device__ __forceinline__ float lo32(unsigned long long v) {
    return __uint_as_float((unsigned)v);
}
__device__ __forceinline__ float hi32(unsigned long long v) {
    return __uint_as_float((unsigned)(v >> 32));
}

// Phase 1: block = (batch b, query tile qt, ref chunk rc).
// 2048 queries x 1024 refs per block. 16KB smem, 512 threads (4 warps/SMSP).
__global__ __launch_bounds__(TPB) void chamfer_phase1(
    const float* __restrict__ pc2,       // queries  [B,3,N]
    const float* __restrict__ pc1w) {    // refs     [B,3,N]
    int blk = blockIdx.x;
    int rc = blk % RC;
    int qt = (blk / RC) % QT;
    int b  = blk / (RC * QT);

    const float* __restrict__ qry = pc2  + b * 3 * NQ;
    const float* __restrict__ ref = pc1w + b * 3 * NQ;

    __shared__ float sx[CHUNK];
    __shared__ float sy[CHUNK];
    __shared__ float sz[CHUNK];
    __shared__ float sh[CHUNK];   // r^2 / 2

    int tid = threadIdx.x;
    int rbase = rc * CHUNK;

    // Cooperative coalesced load of the ref chunk.
    for (int i = tid; i < CHUNK; i += TPB) {
        float x = ref[rbase + i];
        float y = ref[NQ + rbase + i];
        float z = ref[2 * NQ + rbase + i];
        sx[i] = x; sy[i] = y; sz[i] = z;
        sh[i] = 0.5f * (x * x + y * y + z * z);
    }
    __syncthreads();

    // Register tile of QPT queries, broadcast as packed f32x2 negatives.
    unsigned long long nqx[QPT], nqy[QPT], nqz[QPT];
    float q2h[QPT];
    int qidx[QPT];
#pragma unroll
    for (int q = 0; q < QPT; q++) {
        int qi = qt * (TPB * QPT) + q * TPB + tid;
        qidx[q] = qi;
        float x = qry[qi];
        float y = qry[NQ + qi];
        float z = qry[2 * NQ + qi];
        nqx[q] = pack2(-x, -x);
        nqy[q] = pack2(-y, -y);
        nqz[q] = pack2(-z, -z);
        q2h[q] = 0.5f * (x * x + y * y + z * z);
    }

    float mlo[QPT], mhi[QPT];
#pragma unroll
    for (int q = 0; q < QPT; q++) { mlo[q] = 3.0e38f; mhi[q] = 3.0e38f; }

    const ulonglong2* __restrict__ px = (const ulonglong2*)sx;
    const ulonglong2* __restrict__ py = (const ulonglong2*)sy;
    const ulonglong2* __restrict__ pz = (const ulonglong2*)sz;
    const ulonglong2* __restrict__ ph = (const ulonglong2*)sh;

    // Main loop: 4 refs (two packed pairs via LDS.128) x QPT queries per iter.
    // Per iter: 4 LDS.128 + QPT*6 FFMA2 + QPT*4 FMNMX.
#pragma unroll 2
    for (int j = 0; j < CHUNK4; j++) {
        ulonglong2 X = px[j];
        ulonglong2 Y = py[j];
        ulonglong2 Z = pz[j];
        ulonglong2 H = ph[j];
#pragma unroll
        for (int q = 0; q < QPT; q++) {
            unsigned long long t0 = ffma2(nqx[q], X.x, H.x);
            t0 = ffma2(nqy[q], Y.x, t0);
            t0 = ffma2(nqz[q], Z.x, t0);
            unsigned long long t1 = ffma2(nqx[q], X.y, H.y);
            t1 = ffma2(nqy[q], Y.y, t1);
            t1 = ffma2(nqz[q], Z.y, t1);
            // combine independent values first, then one chain-link per iter
            mlo[q] = fminf(mlo[q], fminf(lo32(t0), lo32(t1)));
            mhi[q] = fminf(mhi[q], fminf(hi32(t0), hi32(t1)));
        }
    }

#pragma unroll
    for (int q = 0; q < QPT; q++) {
        g_smin[(b * RC + rc) * NQ + qidx[q]] = q2h[q] + fminf(mlo[q], mhi[q]);
    }
}

// Phase 2a: 128 blocks x 256 threads. One scratch entry per thread:
// min over RC chunks, clamp, 2x, deterministic block tree-sum -> g_part.
__global__ __launch_bounds__(256) void chamfer_phase2a() {
    __shared__ float red[256];
    int tid = threadIdx.x;
    int i = blockIdx.x * 256 + tid;       // 128*256 == BQ*NQ
    int b  = i >> 13;                     // / NQ
    int qi = i & (NQ - 1);
    const float* p = &g_smin[b * RC * NQ + qi];
    float s = p[0];
#pragma unroll
    for (int c = 1; c < RC; c++) s = fminf(s, p[c * NQ]);
    red[tid] = fmaxf(2.0f * s, 0.0f);     // nn squared dist, clamped
    __syncthreads();
#pragma unroll
    for (int st = 128; st > 0; st >>= 1) {
        if (tid < st) red[tid] += red[tid + st];
        __syncthreads();
    }
    if (tid == 0) g_part[blockIdx.x] = red[0];
}

// Phase 2b: one block, deterministic tree-sum of 128 partials.
// loss = 2 * mean_b(sum) = (2/BQ) * total.
__global__ __launch_bounds__(128) void chamfer_phase2b(float* __restrict__ out) {
    __shared__ float red[128];
    int tid = threadIdx.x;
    red[tid] = g_part[tid];
    __syncthreads();
#pragma unroll
    for (int st = 64; st > 0; st >>= 1) {
        if (tid < st) red[tid] += red[tid + st];
        __syncthreads();
    }
    if (tid == 0) out[0] = red[0] * (2.0f / BQ);
}

extern "C" void kernel_launch(void* const* d_in, const int* in_sizes, int n_in,
                              void* d_out, int out_size) {
    const float* pc2  = (const float*)d_in[0];   // queries source
    const float* pc1w = (const float*)d_in[1];   // refs source
    float* out = (float*)d_out;

    chamfer_phase1<<<BQ * QT * RC, TPB>>>(pc2, pc1w);
    chamfer_phase2a<<<128, 256>>>();
    chamfer_phase2b<<<1, 128>>>(out);
}

// round 9
// speedup vs baseline: 2.0702x; 1.0402x over previous
#include <cuda_runtime.h>

#define BQ    4            // batches
#define NQ    8192         // points per cloud
#define TPB   512          // threads per block (phase 1)
#define QPT   4            // queries per thread per pass
#define NPASS 4            // passes: NPASS*TPB*QPT == NQ
#define NSL   37           // ref slices per batch  (4*37 == 148 blocks)
#define SBASE 221          // 8192 = 37*221 + 15  -> slices 0..14 have 222
#define SREM  15
#define NPAD  224          // padded slice length (multiple of 4)
#define NITER (NPAD / 4)   // 56 inner iterations, 4 refs each

// Phase-1 scratch: s = q^2/2 + min_slice(r^2/2 - q.r), per [batch][slice][query]
__device__ float g_smin[BQ * NSL * NQ];
// Phase-2a partials
__device__ float g_part[128];

__device__ __forceinline__ unsigned long long pack2(float a, float b) {
    unsigned long long r;
    asm("mov.b64 %0, {%1, %2};" : "=l"(r) : "f"(a), "f"(b));
    return r;
}
__device__ __forceinline__ unsigned long long ffma2(unsigned long long a,
                                                    unsigned long long b,
                                                    unsigned long long c) {
    unsigned long long d;
    asm("fma.rn.f32x2 %0, %1, %2, %3;" : "=l"(d) : "l"(a), "l"(b), "l"(c));
    return d;
}
__device__ __forceinline__ float lo32(unsigned long long v) {
    return __uint_as_float((unsigned)v);
}
__device__ __forceinline__ float hi32(unsigned long long v) {
    return __uint_as_float((unsigned)(v >> 32));
}

// Phase 1: 148 blocks = (batch b, ref slice sl). Slice (~222 refs) lives in
// smem; block sweeps ALL 8192 queries in 4 passes of 2048 (QPT=4 regs/thread).
__global__ __launch_bounds__(TPB) void chamfer_phase1(
    const float* __restrict__ pc2,       // queries  [B,3,N]
    const float* __restrict__ pc1w) {    // refs     [B,3,N]
    int blk = blockIdx.x;
    int sl = blk % NSL;
    int b  = blk / NSL;

    const float* __restrict__ qry = pc2  + b * 3 * NQ;
    const float* __restrict__ ref = pc1w + b * 3 * NQ;

    __shared__ float sx[NPAD];
    __shared__ float sy[NPAD];
    __shared__ float sz[NPAD];
    __shared__ float sh[NPAD];   // r^2 / 2  (padding: +3e38 sentinel)

    int tid = threadIdx.x;
    int start = sl * SBASE + min(sl, SREM);
    int ssize = SBASE + (sl < SREM ? 1 : 0);

    // Load the ref slice (pad with sentinels that can never win the min).
    for (int i = tid; i < NPAD; i += TPB) {
        if (i < ssize) {
            float x = ref[start + i];
            float y = ref[NQ + start + i];
            float z = ref[2 * NQ + start + i];
            sx[i] = x; sy[i] = y; sz[i] = z;
            sh[i] = 0.5f * (x * x + y * y + z * z);
        } else {
            sx[i] = 0.0f; sy[i] = 0.0f; sz[i] = 0.0f;
            sh[i] = 3.0e38f;
        }
    }
    __syncthreads();

    const ulonglong2* __restrict__ px = (const ulonglong2*)sx;
    const ulonglong2* __restrict__ py = (const ulonglong2*)sy;
    const ulonglong2* __restrict__ pz = (const ulonglong2*)sz;
    const ulonglong2* __restrict__ ph = (const ulonglong2*)sh;

    for (int pass = 0; pass < NPASS; pass++) {
        // Register tile of QPT queries, broadcast as packed f32x2 negatives.
        unsigned long long nqx[QPT], nqy[QPT], nqz[QPT];
        float q2h[QPT];
        int qidx[QPT];
#pragma unroll
        for (int q = 0; q < QPT; q++) {
            int qi = pass * (TPB * QPT) + q * TPB + tid;
            qidx[q] = qi;
            float x = qry[qi];
            float y = qry[NQ + qi];
            float z = qry[2 * NQ + qi];
            nqx[q] = pack2(-x, -x);
            nqy[q] = pack2(-y, -y);
            nqz[q] = pack2(-z, -z);
            q2h[q] = 0.5f * (x * x + y * y + z * z);
        }

        float mlo[QPT], mhi[QPT];
#pragma unroll
        for (int q = 0; q < QPT; q++) { mlo[q] = 3.0e38f; mhi[q] = 3.0e38f; }

        // 4 refs (two packed pairs via broadcast LDS.128) x QPT queries / iter.
#pragma unroll 2
        for (int j = 0; j < NITER; j++) {
            ulonglong2 X = px[j];
            ulonglong2 Y = py[j];
            ulonglong2 Z = pz[j];
            ulonglong2 H = ph[j];
#pragma unroll
            for (int q = 0; q < QPT; q++) {
                unsigned long long t0 = ffma2(nqx[q], X.x, H.x);
                t0 = ffma2(nqy[q], Y.x, t0);
                t0 = ffma2(nqz[q], Z.x, t0);
                unsigned long long t1 = ffma2(nqx[q], X.y, H.y);
                t1 = ffma2(nqy[q], Y.y, t1);
                t1 = ffma2(nqz[q], Z.y, t1);
                mlo[q] = fminf(mlo[q], fminf(lo32(t0), lo32(t1)));
                mhi[q] = fminf(mhi[q], fminf(hi32(t0), hi32(t1)));
            }
        }

#pragma unroll
        for (int q = 0; q < QPT; q++) {
            g_smin[(b * NSL + sl) * NQ + qidx[q]] = q2h[q] + fminf(mlo[q], mhi[q]);
        }
    }
}

// Phase 2a: 128 blocks x 256 threads, one query per thread: min over NSL
// slices, clamp, 2x, deterministic block tree-sum -> g_part.
__global__ __launch_bounds__(256) void chamfer_phase2a() {
    __shared__ float red[256];
    int tid = threadIdx.x;
    int i = blockIdx.x * 256 + tid;       // 128*256 == BQ*NQ
    int b  = i >> 13;                     // / NQ
    int qi = i & (NQ - 1);
    const float* p = &g_smin[b * NSL * NQ + qi];
    float s = p[0];
#pragma unroll
    for (int c = 1; c < NSL; c++) s = fminf(s, p[c * NQ]);
    red[tid] = fmaxf(2.0f * s, 0.0f);     // nn squared dist, clamped
    __syncthreads();
#pragma unroll
    for (int st = 128; st > 0; st >>= 1) {
        if (tid < st) red[tid] += red[tid + st];
        __syncthreads();
    }
    if (tid == 0) g_part[blockIdx.x] = red[0];
}

// Phase 2b: one block, deterministic tree-sum of 128 partials.
// loss = 2 * mean_b(sum) = (2/BQ) * total.
__global__ __launch_bounds__(128) void chamfer_phase2b(float* __restrict__ out) {
    __shared__ float red[128];
    int tid = threadIdx.x;
    red[tid] = g_part[tid];
    __syncthreads();
#pragma unroll
    for (int st = 64; st > 0; st >>= 1) {
        if (tid < st) red[tid] += red[tid + st];
        __syncthreads();
    }
    if (tid == 0) out[0] = red[0] * (2.0f / BQ);
}

extern "C" void kernel_launch(void* const* d_in, const int* in_sizes, int n_in,
                              void* d_out, int out_size) {
    const float* pc2  = (const float*)d_in[0];   // queries source
    const float* pc1w = (const float*)d_in[1];   // refs source
    float* out = (float*)d_out;

    chamfer_phase1<<<BQ * NSL, TPB>>>(pc2, pc1w);
    chamfer_phase2a<<<128, 256>>>();
    chamfer_phase2b<<<1, 128>>>(out);
}